// round 6
// baseline (speedup 1.0000x reference)
#include <cuda_runtime.h>
#include <cuda_bf16.h>
#include <cstdint>

// GCN: 3 layers, N=50000, E=600000, D=128.
// Out layout: [total | x0 | x1 | x2 | x3], each n*D f32.
// GEMM via mma.sync bf16 split-precision; CSR aggregate; fused preprocessing.

#define DD 128
#define MAXN 50016
#define MAXE 600000
#define SCAN_B 512
#define LDT 136

// Scratch (device globals; no allocation allowed)
__device__ float g_y[(size_t)MAXN * DD];
__device__ int   g_src[MAXE];
__device__ int   g_dst[MAXE];
__device__ int   g_csrc[MAXE];
__device__ float g_cw[MAXE];
__device__ float g_dinv[MAXN];
__device__ int   g_deg[MAXN];
__device__ int   g_rowstart[MAXN];
__device__ int   g_cursor[MAXN];
__device__ int   g_partial[128];   // lookback prefix flags (-1 = not ready)
__device__ int   g_ticket;
__device__ int   g_is64;

// ---------------------------------------------------------------------------
__device__ __forceinline__ uint32_t smem_u32(const void* p) {
    uint32_t a;
    asm("{ .reg .u64 t; cvta.to.shared.u64 t, %1; cvt.u32.u64 %0, t; }" : "=r"(a) : "l"(p));
    return a;
}
__device__ __forceinline__ void ldm_x4(uint32_t* r, uint32_t addr) {
    asm volatile("ldmatrix.sync.aligned.m8n8.x4.shared.b16 {%0,%1,%2,%3}, [%4];"
                 : "=r"(r[0]), "=r"(r[1]), "=r"(r[2]), "=r"(r[3]) : "r"(addr));
}
__device__ __forceinline__ void ldm_x4_t(uint32_t* r, uint32_t addr) {
    asm volatile("ldmatrix.sync.aligned.m8n8.x4.trans.shared.b16 {%0,%1,%2,%3}, [%4];"
                 : "=r"(r[0]), "=r"(r[1]), "=r"(r[2]), "=r"(r[3]) : "r"(addr));
}
__device__ __forceinline__ void mma_bf16(float* c, const uint32_t* a, const uint32_t* b) {
    asm volatile(
        "mma.sync.aligned.m16n8k16.row.col.f32.bf16.bf16.f32 "
        "{%0,%1,%2,%3}, {%4,%5,%6,%7}, {%8,%9}, {%0,%1,%2,%3};"
        : "+f"(c[0]), "+f"(c[1]), "+f"(c[2]), "+f"(c[3])
        : "r"(a[0]), "r"(a[1]), "r"(a[2]), "r"(a[3]), "r"(b[0]), "r"(b[1]));
}
__device__ __forceinline__ uint32_t bfbits(float v) {
    return (uint32_t)__bfloat16_as_ushort(__float2bfloat16(v));
}
__device__ __forceinline__ float bfval(uint32_t b) {
    return __bfloat162float(__ushort_as_bfloat16((unsigned short)b));
}

#define T_ELE (128 * LDT)
#define GEMM_SMEM (4 * T_ELE * 2)

// ---------------------------------------------------------------------------
// GEMM: g_y = x @ W via HMMA (unchanged from R4 — verified).
__global__ __launch_bounds__(256) void k_gemm_mma(const float* __restrict__ x,
                                                  const float* __restrict__ W, int n) {
    extern __shared__ __align__(16) char smem[];
    __nv_bfloat16* AH = (__nv_bfloat16*)smem;
    __nv_bfloat16* AL = AH + T_ELE;
    __nv_bfloat16* BH = AL + T_ELE;
    __nv_bfloat16* BL = BH + T_ELE;

    int tid = threadIdx.x;
    int wid = tid >> 5, lane = tid & 31;
    int row0 = blockIdx.x * 128;

#pragma unroll
    for (int i = 0; i < 16; i++) {
        int idx = tid + i * 256;
        int r = idx >> 5, f = idx & 31;
        int grow = row0 + r;
        float4 v = make_float4(0.f, 0.f, 0.f, 0.f);
        if (grow < n) v = *(const float4*)(x + (size_t)grow * DD + f * 4);
        uint32_t hx = bfbits(v.x), hy = bfbits(v.y), hz = bfbits(v.z), hw = bfbits(v.w);
        uint2 hh = make_uint2((hy << 16) | hx, (hw << 16) | hz);
        uint2 ll = make_uint2((bfbits(v.y - bfval(hy)) << 16) | bfbits(v.x - bfval(hx)),
                              (bfbits(v.w - bfval(hw)) << 16) | bfbits(v.z - bfval(hz)));
        *(uint2*)(AH + r * LDT + f * 4) = hh;
        *(uint2*)(AL + r * LDT + f * 4) = ll;
    }
#pragma unroll
    for (int i = 0; i < 16; i++) {
        int idx = tid + i * 256;
        int r = idx >> 5, f = idx & 31;
        float4 v = *(const float4*)(W + (size_t)r * DD + f * 4);
        uint32_t hx = bfbits(v.x), hy = bfbits(v.y), hz = bfbits(v.z), hw = bfbits(v.w);
        uint2 hh = make_uint2((hy << 16) | hx, (hw << 16) | hz);
        uint2 ll = make_uint2((bfbits(v.y - bfval(hy)) << 16) | bfbits(v.x - bfval(hx)),
                              (bfbits(v.w - bfval(hw)) << 16) | bfbits(v.z - bfval(hz)));
        *(uint2*)(BH + r * LDT + f * 4) = hh;
        *(uint2*)(BL + r * LDT + f * 4) = ll;
    }
    __syncthreads();

    int m0 = wid * 16;
    uint32_t a_off_h = smem_u32(AH + (m0 + (lane & 15)) * LDT + (lane >> 4) * 8);
    uint32_t a_off_l = a_off_h + (uint32_t)(T_ELE * 2);

    float acc[16][4];
#pragma unroll
    for (int j = 0; j < 16; j++)
#pragma unroll
        for (int q = 0; q < 4; q++) acc[j][q] = 0.0f;

#pragma unroll
    for (int k = 0; k < 8; k++) {
        uint32_t ah[4], al[4];
        ldm_x4(ah, a_off_h + k * 32);
        ldm_x4(al, a_off_l + k * 32);
        uint32_t b_base = smem_u32(BH + (k * 16 + (lane & 15)) * LDT + (lane >> 4) * 8);
#pragma unroll
        for (int j2 = 0; j2 < 8; j2++) {
            uint32_t bh[4], bl[4];
            ldm_x4_t(bh, b_base + j2 * 32);
            ldm_x4_t(bl, b_base + j2 * 32 + (uint32_t)(T_ELE * 2));
            mma_bf16(acc[2 * j2],     ah, bh);
            mma_bf16(acc[2 * j2],     ah, bl);
            mma_bf16(acc[2 * j2],     al, bh);
            mma_bf16(acc[2 * j2 + 1], ah, bh + 2);
            mma_bf16(acc[2 * j2 + 1], ah, bl + 2);
            mma_bf16(acc[2 * j2 + 1], al, bh + 2);
        }
    }

    int r_lo = row0 + m0 + (lane >> 2);
    int r_hi = r_lo + 8;
    int cbase = (lane & 3) * 2;
#pragma unroll
    for (int j = 0; j < 16; j++) {
        int col = j * 8 + cbase;
        if (r_lo < n) *(float2*)(g_y + (size_t)r_lo * DD + col) = make_float2(acc[j][0], acc[j][1]);
        if (r_hi < n) *(float2*)(g_y + (size_t)r_hi * DD + col) = make_float2(acc[j][2], acc[j][3]);
    }
}

// ---------------------------------------------------------------------------
// P1: zero deg, reset scan state, detect dtype.
__global__ void k_prep1(const unsigned int* __restrict__ raw, int n) {
    int i = blockIdx.x * blockDim.x + threadIdx.x;
    if (i < n) g_deg[i] = 0;
    if (i < 128) g_partial[i] = -1;
    if (i == 0) {
        g_ticket = 0;
        int ok64 = (raw[1] == 0u) && (raw[3] == 0u) && (raw[5] == 0u) &&
                   (raw[7] == 0u) && (raw[9] == 0u) && (raw[11] == 0u);
        g_is64 = ok64 ? 1 : 0;
    }
}

// P2: convert edges + count degree; tail blocks copy x0.
__global__ void k_prep2(const void* __restrict__ raw, int E, int nb_e,
                        const float* __restrict__ emb, float* __restrict__ x0, int n) {
    int b = blockIdx.x;
    if (b < nb_e) {
        int e = b * blockDim.x + threadIdx.x;
        if (e >= E) return;
        int s, d;
        if (g_is64) {
            const long long* p = (const long long*)raw;
            s = (int)p[e]; d = (int)p[e + E];
        } else {
            const int* p = (const int*)raw;
            s = p[e]; d = p[e + E];
        }
        g_src[e] = s; g_dst[e] = d;
        atomicAdd(&g_deg[d], 1);
    } else {
        int i = (b - nb_e) * blockDim.x + threadIdx.x;
        if (i < n * (DD / 4)) ((float4*)x0)[i] = ((const float4*)emb)[i];
    }
}

// P3: single-pass exclusive scan (decoupled lookback) + dinv + cursor init.
__global__ __launch_bounds__(SCAN_B) void k_scan_lb(int n) {
    __shared__ int sh[SCAN_B];
    __shared__ int sh_bid;
    __shared__ int sh_prev;
    if (threadIdx.x == 0) sh_bid = atomicAdd(&g_ticket, 1);
    __syncthreads();
    int bid = sh_bid;
    int i = bid * SCAN_B + threadIdx.x;
    int v = (i < n) ? g_deg[i] : 0;
    if (i < n) g_dinv[i] = rsqrtf((float)(v + 1));
    sh[threadIdx.x] = v;
    __syncthreads();
#pragma unroll
    for (int off = 1; off < SCAN_B; off <<= 1) {
        int t = (threadIdx.x >= off) ? sh[threadIdx.x - off] : 0;
        __syncthreads();
        sh[threadIdx.x] += t;
        __syncthreads();
    }
    if (threadIdx.x == 0) {
        int prev = 0;
        if (bid > 0) {
            do { prev = atomicAdd(&g_partial[bid - 1], 0); } while (prev < 0);
        }
        atomicExch(&g_partial[bid], prev + sh[SCAN_B - 1]);
        sh_prev = prev;
    }
    __syncthreads();
    if (i < n) {
        int ex = sh[threadIdx.x] - v + sh_prev;
        g_rowstart[i] = ex;
        g_cursor[i]   = ex;
    }
}

// P4: fill CSR slots with src + weight.
__global__ void k_fill(int E) {
    int e = blockIdx.x * blockDim.x + threadIdx.x;
    if (e >= E) return;
    int s = g_src[e], d = g_dst[e];
    int pos = atomicAdd(&g_cursor[d], 1);
    g_csrc[pos] = s;
    g_cw[pos]   = g_dinv[s] * g_dinv[d];
}

// ---------------------------------------------------------------------------
// Aggregate: xout = bias + y*dinv^2 + sum_e y[src]*w.  One warp per node.
// If total!=nullptr (last layer), also writes total = x0+x1+x2+xout.
__global__ __launch_bounds__(256) void k_aggregate(const float* __restrict__ bias,
                                                   float* __restrict__ xout,
                                                   float* __restrict__ total,
                                                   const float* __restrict__ xbase,
                                                   int n) {
    int t = blockIdx.x * blockDim.x + threadIdx.x;
    int node = t >> 5, lane = t & 31;
    if (node >= n) return;

    float s = g_dinv[node];
    s = s * s;
    float4 bb = ((const float4*)bias)[lane];
    float4 v  = ((const float4*)g_y)[(size_t)node * 32 + lane];
    float ax = fmaf(v.x, s, bb.x);
    float ay = fmaf(v.y, s, bb.y);
    float az = fmaf(v.z, s, bb.z);
    float aw = fmaf(v.w, s, bb.w);

    int st  = g_rowstart[node];
    int cnt = g_deg[node];
    int k = 0;
    for (; k + 3 < cnt; k += 4) {
        int   s0 = g_csrc[st + k],     s1 = g_csrc[st + k + 1];
        int   s2 = g_csrc[st + k + 2], s3 = g_csrc[st + k + 3];
        float w0 = g_cw[st + k],       w1 = g_cw[st + k + 1];
        float w2 = g_cw[st + k + 2],   w3 = g_cw[st + k + 3];
        float4 v0 = ((const float4*)g_y)[(size_t)s0 * 32 + lane];
        float4 v1 = ((const float4*)g_y)[(size_t)s1 * 32 + lane];
        float4 v2 = ((const float4*)g_y)[(size_t)s2 * 32 + lane];
        float4 v3 = ((const float4*)g_y)[(size_t)s3 * 32 + lane];
        ax = fmaf(v0.x, w0, ax); ay = fmaf(v0.y, w0, ay);
        az = fmaf(v0.z, w0, az); aw = fmaf(v0.w, w0, aw);
        ax = fmaf(v1.x, w1, ax); ay = fmaf(v1.y, w1, ay);
        az = fmaf(v1.z, w1, az); aw = fmaf(v1.w, w1, aw);
        ax = fmaf(v2.x, w2, ax); ay = fmaf(v2.y, w2, ay);
        az = fmaf(v2.z, w2, az); aw = fmaf(v2.w, w2, aw);
        ax = fmaf(v3.x, w3, ax); ay = fmaf(v3.y, w3, ay);
        az = fmaf(v3.z, w3, az); aw = fmaf(v3.w, w3, aw);
    }
    for (; k < cnt; k++) {
        int   s0 = g_csrc[st + k];
        float w0 = g_cw[st + k];
        float4 v0 = ((const float4*)g_y)[(size_t)s0 * 32 + lane];
        ax = fmaf(v0.x, w0, ax); ay = fmaf(v0.y, w0, ay);
        az = fmaf(v0.z, w0, az); aw = fmaf(v0.w, w0, aw);
    }
    size_t idx = (size_t)node * 32 + lane;
    ((float4*)xout)[idx] = make_float4(ax, ay, az, aw);

    if (total) {
        size_t nd4 = (size_t)n * 32;
        const float4* xb = (const float4*)xbase;
        float4 a = xb[idx], b2 = xb[nd4 + idx], c = xb[2 * nd4 + idx];
        ((float4*)total)[idx] = make_float4(a.x + b2.x + c.x + ax,
                                            a.y + b2.y + c.y + ay,
                                            a.z + b2.z + c.z + az,
                                            a.w + b2.w + c.w + aw);
    }
}

// ---------------------------------------------------------------------------
extern "C" void kernel_launch(void* const* d_in, const int* in_sizes, int n_in,
                              void* d_out, int out_size) {
    const float* item_emb = (const float*)d_in[0];
    const float* weights  = (const float*)d_in[1];
    const float* biases   = (const float*)d_in[2];
    const void*  edge_raw = d_in[3];

    int n = out_size / (5 * DD);
    int E = in_sizes[3] / 2;
    int emb_off = in_sizes[0] - n * DD;
    float* out = (float*)d_out;

    static bool attr_set = false;
    if (!attr_set) {
        cudaFuncSetAttribute(k_gemm_mma, cudaFuncAttributeMaxDynamicSharedMemorySize, GEMM_SMEM);
        attr_set = true;
    }

    const int TB = 256;
    int nb_n    = (n + TB - 1) / TB;
    int nb_e    = (E + TB - 1) / TB;
    int nb_nd4  = (n * 32 + TB - 1) / TB;
    int nb_scan = (n + SCAN_B - 1) / SCAN_B;

    // Preprocessing: 4 kernels
    k_prep1<<<nb_n, TB>>>((const unsigned int*)edge_raw, n);
    k_prep2<<<nb_e + nb_nd4, TB>>>(edge_raw, E, nb_e,
                                   item_emb + emb_off, out + (size_t)n * DD, n);
    k_scan_lb<<<nb_scan, SCAN_B>>>(n);
    k_fill<<<nb_e, TB>>>(E);

    long long agg_threads = (long long)n * 32;
    int nb_agg = (int)((agg_threads + TB - 1) / TB);
    int nb_gemm = (n + 127) / 128;
    for (int l = 0; l < 3; l++) {
        const float* xin = out + (size_t)(l + 1) * n * DD;
        float* xout      = out + (size_t)(l + 2) * n * DD;
        k_gemm_mma<<<nb_gemm, 256, GEMM_SMEM>>>(xin, weights + (size_t)l * DD * DD, n);
        k_aggregate<<<nb_agg, TB>>>(biases + (size_t)l * DD, xout,
                                    (l == 2) ? out : nullptr,
                                    out + (size_t)n * DD, n);
    }
}

// round 9
// speedup vs baseline: 1.1722x; 1.1722x over previous
#include <cuda_runtime.h>
#include <cuda_bf16.h>
#include <cstdint>

// GCN: 3 layers, N=50000, E=600000, D=128.
// Out layout: [total | x0 | x1 | x2 | x3], each n*D f32.
// HMMA split-precision GEMM; CSR aggregate (no atomics in fill); fused prep.

#define DD 128
#define MAXN 50016
#define MAXE 600000
#define SCAN_B 512
#define LDT 136

// Scratch (device globals; no allocation allowed)
__device__ float g_y[(size_t)MAXN * DD];
__device__ int   g_src[MAXE];
__device__ int   g_dst[MAXE];
__device__ int   g_off[MAXE];      // slot within dst bucket (from deg atomic)
__device__ int   g_csrc[MAXE];
__device__ float g_cw[MAXE];
__device__ float g_dinv[MAXN];
__device__ int   g_deg[MAXN];
__device__ int   g_rowstart[MAXN];
__device__ int   g_bsum[256];
__device__ int   g_boff[256];
__device__ int   g_is64;

// ---------------------------------------------------------------------------
__device__ __forceinline__ uint32_t smem_u32(const void* p) {
    uint32_t a;
    asm("{ .reg .u64 t; cvta.to.shared.u64 t, %1; cvt.u32.u64 %0, t; }" : "=r"(a) : "l"(p));
    return a;
}
__device__ __forceinline__ void ldm_x4(uint32_t* r, uint32_t addr) {
    asm volatile("ldmatrix.sync.aligned.m8n8.x4.shared.b16 {%0,%1,%2,%3}, [%4];"
                 : "=r"(r[0]), "=r"(r[1]), "=r"(r[2]), "=r"(r[3]) : "r"(addr));
}
__device__ __forceinline__ void ldm_x4_t(uint32_t* r, uint32_t addr) {
    asm volatile("ldmatrix.sync.aligned.m8n8.x4.trans.shared.b16 {%0,%1,%2,%3}, [%4];"
                 : "=r"(r[0]), "=r"(r[1]), "=r"(r[2]), "=r"(r[3]) : "r"(addr));
}
__device__ __forceinline__ void mma_bf16(float* c, const uint32_t* a, const uint32_t* b) {
    asm volatile(
        "mma.sync.aligned.m16n8k16.row.col.f32.bf16.bf16.f32 "
        "{%0,%1,%2,%3}, {%4,%5,%6,%7}, {%8,%9}, {%0,%1,%2,%3};"
        : "+f"(c[0]), "+f"(c[1]), "+f"(c[2]), "+f"(c[3])
        : "r"(a[0]), "r"(a[1]), "r"(a[2]), "r"(a[3]), "r"(b[0]), "r"(b[1]));
}
__device__ __forceinline__ uint32_t bfbits(float v) {
    return (uint32_t)__bfloat16_as_ushort(__float2bfloat16(v));
}
__device__ __forceinline__ float bfval(uint32_t b) {
    return __bfloat162float(__ushort_as_bfloat16((unsigned short)b));
}

#define T_ELE (128 * LDT)
#define GEMM_SMEM (4 * T_ELE * 2)

// ---------------------------------------------------------------------------
// GEMM: g_y = x @ W via HMMA split precision (verified in R4).
__global__ __launch_bounds__(256) void k_gemm_mma(const float* __restrict__ x,
                                                  const float* __restrict__ W, int n) {
    extern __shared__ __align__(16) char smem[];
    __nv_bfloat16* AH = (__nv_bfloat16*)smem;
    __nv_bfloat16* AL = AH + T_ELE;
    __nv_bfloat16* BH = AL + T_ELE;
    __nv_bfloat16* BL = BH + T_ELE;

    int tid = threadIdx.x;
    int wid = tid >> 5, lane = tid & 31;
    int row0 = blockIdx.x * 128;

#pragma unroll
    for (int i = 0; i < 16; i++) {
        int idx = tid + i * 256;
        int r = idx >> 5, f = idx & 31;
        int grow = row0 + r;
        float4 v = make_float4(0.f, 0.f, 0.f, 0.f);
        if (grow < n) v = *(const float4*)(x + (size_t)grow * DD + f * 4);
        uint32_t hx = bfbits(v.x), hy = bfbits(v.y), hz = bfbits(v.z), hw = bfbits(v.w);
        uint2 hh = make_uint2((hy << 16) | hx, (hw << 16) | hz);
        uint2 ll = make_uint2((bfbits(v.y - bfval(hy)) << 16) | bfbits(v.x - bfval(hx)),
                              (bfbits(v.w - bfval(hw)) << 16) | bfbits(v.z - bfval(hz)));
        *(uint2*)(AH + r * LDT + f * 4) = hh;
        *(uint2*)(AL + r * LDT + f * 4) = ll;
    }
#pragma unroll
    for (int i = 0; i < 16; i++) {
        int idx = tid + i * 256;
        int r = idx >> 5, f = idx & 31;
        float4 v = *(const float4*)(W + (size_t)r * DD + f * 4);
        uint32_t hx = bfbits(v.x), hy = bfbits(v.y), hz = bfbits(v.z), hw = bfbits(v.w);
        uint2 hh = make_uint2((hy << 16) | hx, (hw << 16) | hz);
        uint2 ll = make_uint2((bfbits(v.y - bfval(hy)) << 16) | bfbits(v.x - bfval(hx)),
                              (bfbits(v.w - bfval(hw)) << 16) | bfbits(v.z - bfval(hz)));
        *(uint2*)(BH + r * LDT + f * 4) = hh;
        *(uint2*)(BL + r * LDT + f * 4) = ll;
    }
    __syncthreads();

    int m0 = wid * 16;
    uint32_t a_off_h = smem_u32(AH + (m0 + (lane & 15)) * LDT + (lane >> 4) * 8);
    uint32_t a_off_l = a_off_h + (uint32_t)(T_ELE * 2);

    float acc[16][4];
#pragma unroll
    for (int j = 0; j < 16; j++)
#pragma unroll
        for (int q = 0; q < 4; q++) acc[j][q] = 0.0f;

#pragma unroll
    for (int k = 0; k < 8; k++) {
        uint32_t ah[4], al[4];
        ldm_x4(ah, a_off_h + k * 32);
        ldm_x4(al, a_off_l + k * 32);
        uint32_t b_base = smem_u32(BH + (k * 16 + (lane & 15)) * LDT + (lane >> 4) * 8);
#pragma unroll
        for (int j2 = 0; j2 < 8; j2++) {
            uint32_t bh[4], bl[4];
            ldm_x4_t(bh, b_base + j2 * 32);
            ldm_x4_t(bl, b_base + j2 * 32 + (uint32_t)(T_ELE * 2));
            mma_bf16(acc[2 * j2],     ah, bh);
            mma_bf16(acc[2 * j2],     ah, bl);
            mma_bf16(acc[2 * j2],     al, bh);
            mma_bf16(acc[2 * j2 + 1], ah, bh + 2);
            mma_bf16(acc[2 * j2 + 1], ah, bl + 2);
            mma_bf16(acc[2 * j2 + 1], al, bh + 2);
        }
    }

    int r_lo = row0 + m0 + (lane >> 2);
    int r_hi = r_lo + 8;
    int cbase = (lane & 3) * 2;
#pragma unroll
    for (int j = 0; j < 16; j++) {
        int col = j * 8 + cbase;
        if (r_lo < n) *(float2*)(g_y + (size_t)r_lo * DD + col) = make_float2(acc[j][0], acc[j][1]);
        if (r_hi < n) *(float2*)(g_y + (size_t)r_hi * DD + col) = make_float2(acc[j][2], acc[j][3]);
    }
}

// ---------------------------------------------------------------------------
// P1: zero deg + detect dtype.
__global__ void k_prep1(const unsigned int* __restrict__ raw, int n) {
    int i = blockIdx.x * blockDim.x + threadIdx.x;
    if (i < n) g_deg[i] = 0;
    if (i == 0) {
        int ok64 = (raw[1] == 0u) && (raw[3] == 0u) && (raw[5] == 0u) &&
                   (raw[7] == 0u) && (raw[9] == 0u) && (raw[11] == 0u);
        g_is64 = ok64 ? 1 : 0;
    }
}

// P2: convert edges + count degree (saving slot offset); tail blocks copy x0.
__global__ void k_prep2(const void* __restrict__ raw, int E, int nb_e,
                        const float* __restrict__ emb, float* __restrict__ x0, int n) {
    int b = blockIdx.x;
    if (b < nb_e) {
        int e = b * blockDim.x + threadIdx.x;
        if (e >= E) return;
        int s, d;
        if (g_is64) {
            const long long* p = (const long long*)raw;
            s = (int)p[e]; d = (int)p[e + E];
        } else {
            const int* p = (const int*)raw;
            s = p[e]; d = p[e + E];
        }
        g_src[e] = s; g_dst[e] = d;
        g_off[e] = atomicAdd(&g_deg[d], 1);
    } else {
        int i = (b - nb_e) * blockDim.x + threadIdx.x;
        if (i < n * (DD / 4)) ((float4*)x0)[i] = ((const float4*)emb)[i];
    }
}

// Scan (3-kernel, fully parallel) + dinv folded into pass 1.
__global__ void k_scan1(int n) {
    __shared__ int sh[SCAN_B];
    int i = blockIdx.x * SCAN_B + threadIdx.x;
    int v = (i < n) ? g_deg[i] : 0;
    if (i < n) g_dinv[i] = rsqrtf((float)(v + 1));
    sh[threadIdx.x] = v;
    __syncthreads();
#pragma unroll
    for (int off = 1; off < SCAN_B; off <<= 1) {
        int t = (threadIdx.x >= off) ? sh[threadIdx.x - off] : 0;
        __syncthreads();
        sh[threadIdx.x] += t;
        __syncthreads();
    }
    if (i < n) g_rowstart[i] = sh[threadIdx.x] - v;
    if (threadIdx.x == SCAN_B - 1) g_bsum[blockIdx.x] = sh[SCAN_B - 1];
}

__global__ void k_scan2(int nb) {
    if (threadIdx.x == 0) {
        int run = 0;
        for (int b = 0; b < nb; b++) { g_boff[b] = run; run += g_bsum[b]; }
    }
}

__global__ void k_scan3(int n) {
    int i = blockIdx.x * blockDim.x + threadIdx.x;
    if (i < n) g_rowstart[i] += g_boff[i >> 9];
}

// Fill CSR: pos = rowstart[dst] + off[e].  No atomics.
__global__ void k_fill(int E) {
    int e = blockIdx.x * blockDim.x + threadIdx.x;
    if (e >= E) return;
    int s = g_src[e], d = g_dst[e];
    int pos = g_rowstart[d] + g_off[e];
    g_csrc[pos] = s;
    g_cw[pos]   = g_dinv[s] * g_dinv[d];
}

// ---------------------------------------------------------------------------
// Aggregate: xout = bias + y*dinv^2 + sum_e y[src]*w.  One warp per node.
// On the last layer also writes total = x0+x1+x2+xout.
__global__ __launch_bounds__(256) void k_aggregate(const float* __restrict__ bias,
                                                   float* __restrict__ xout,
                                                   float* __restrict__ total,
                                                   const float* __restrict__ xbase,
                                                   int n) {
    int t = blockIdx.x * blockDim.x + threadIdx.x;
    int node = t >> 5, lane = t & 31;
    if (node >= n) return;

    float s = g_dinv[node];
    s = s * s;
    float4 bb = ((const float4*)bias)[lane];
    float4 v  = ((const float4*)g_y)[(size_t)node * 32 + lane];
    float ax = fmaf(v.x, s, bb.x);
    float ay = fmaf(v.y, s, bb.y);
    float az = fmaf(v.z, s, bb.z);
    float aw = fmaf(v.w, s, bb.w);

    int st  = g_rowstart[node];
    int cnt = g_deg[node];
    int k = 0;
    for (; k + 3 < cnt; k += 4) {
        int   s0 = g_csrc[st + k],     s1 = g_csrc[st + k + 1];
        int   s2 = g_csrc[st + k + 2], s3 = g_csrc[st + k + 3];
        float w0 = g_cw[st + k],       w1 = g_cw[st + k + 1];
        float w2 = g_cw[st + k + 2],   w3 = g_cw[st + k + 3];
        float4 v0 = ((const float4*)g_y)[(size_t)s0 * 32 + lane];
        float4 v1 = ((const float4*)g_y)[(size_t)s1 * 32 + lane];
        float4 v2 = ((const float4*)g_y)[(size_t)s2 * 32 + lane];
        float4 v3 = ((const float4*)g_y)[(size_t)s3 * 32 + lane];
        ax = fmaf(v0.x, w0, ax); ay = fmaf(v0.y, w0, ay);
        az = fmaf(v0.z, w0, az); aw = fmaf(v0.w, w0, aw);
        ax = fmaf(v1.x, w1, ax); ay = fmaf(v1.y, w1, ay);
        az = fmaf(v1.z, w1, az); aw = fmaf(v1.w, w1, aw);
        ax = fmaf(v2.x, w2, ax); ay = fmaf(v2.y, w2, ay);
        az = fmaf(v2.z, w2, az); aw = fmaf(v2.w, w2, aw);
        ax = fmaf(v3.x, w3, ax); ay = fmaf(v3.y, w3, ay);
        az = fmaf(v3.z, w3, az); aw = fmaf(v3.w, w3, aw);
    }
    for (; k < cnt; k++) {
        int   s0 = g_csrc[st + k];
        float w0 = g_cw[st + k];
        float4 v0 = ((const float4*)g_y)[(size_t)s0 * 32 + lane];
        ax = fmaf(v0.x, w0, ax); ay = fmaf(v0.y, w0, ay);
        az = fmaf(v0.z, w0, az); aw = fmaf(v0.w, w0, aw);
    }
    size_t idx = (size_t)node * 32 + lane;
    ((float4*)xout)[idx] = make_float4(ax, ay, az, aw);

    if (total) {
        size_t nd4 = (size_t)n * 32;
        const float4* xb = (const float4*)xbase;
        float4 a = xb[idx], b2 = xb[nd4 + idx], c = xb[2 * nd4 + idx];
        ((float4*)total)[idx] = make_float4(a.x + b2.x + c.x + ax,
                                            a.y + b2.y + c.y + ay,
                                            a.z + b2.z + c.z + az,
                                            a.w + b2.w + c.w + aw);
    }
}

// ---------------------------------------------------------------------------
extern "C" void kernel_launch(void* const* d_in, const int* in_sizes, int n_in,
                              void* d_out, int out_size) {
    const float* item_emb = (const float*)d_in[0];
    const float* weights  = (const float*)d_in[1];
    const float* biases   = (const float*)d_in[2];
    const void*  edge_raw = d_in[3];

    int n = out_size / (5 * DD);
    int E = in_sizes[3] / 2;
    int emb_off = in_sizes[0] - n * DD;
    float* out = (float*)d_out;

    static bool attr_set = false;
    if (!attr_set) {
        cudaFuncSetAttribute(k_gemm_mma, cudaFuncAttributeMaxDynamicSharedMemorySize, GEMM_SMEM);
        attr_set = true;
    }

    const int TB = 256;
    int nb_n    = (n + TB - 1) / TB;
    int nb_e    = (E + TB - 1) / TB;
    int nb_nd4  = (n * 32 + TB - 1) / TB;
    int nb_scan = (n + SCAN_B - 1) / SCAN_B;

    k_prep1<<<nb_n, TB>>>((const unsigned int*)edge_raw, n);
    k_prep2<<<nb_e + nb_nd4, TB>>>(edge_raw, E, nb_e,
                                   item_emb + emb_off, out + (size_t)n * DD, n);
    k_scan1<<<nb_scan, SCAN_B>>>(n);
    k_scan2<<<1, 32>>>(nb_scan);
    k_scan3<<<nb_n, TB>>>(n);
    k_fill<<<nb_e, TB>>>(E);

    long long agg_threads = (long long)n * 32;
    int nb_agg = (int)((agg_threads + TB - 1) / TB);
    int nb_gemm = (n + 127) / 128;
    for (int l = 0; l < 3; l++) {
        const float* xin = out + (size_t)(l + 1) * n * DD;
        float* xout      = out + (size_t)(l + 2) * n * DD;
        k_gemm_mma<<<nb_gemm, 256, GEMM_SMEM>>>(xin, weights + (size_t)l * DD * DD, n);
        k_aggregate<<<nb_agg, TB>>>(biases + (size_t)l * DD, xout,
                                    (l == 2) ? out : nullptr,
                                    out + (size_t)n * DD, n);
    }
}

// round 11
// speedup vs baseline: 1.2161x; 1.0374x over previous
#include <cuda_runtime.h>
#include <cuda_bf16.h>
#include <cstdint>

// GCN: 3 layers, N=50000, E=600000, D=128.
// Out layout: [total | x0 | x1 | x2 | x3], each n*D f32.
// HMMA split-precision GEMM; CSR aggregate; single-stream (graph-safe).

#define DD 128
#define MAXN 50016
#define MAXE 600000
#define SCAN_B 512
#define LDT 136

// Scratch (device globals; no allocation allowed)
__device__ float g_y[(size_t)MAXN * DD];
__device__ int   g_src[MAXE];
__device__ int   g_dst[MAXE];
__device__ int   g_off[MAXE];
__device__ int   g_csrc[MAXE];
__device__ float g_cw[MAXE];       // = dinv[src]  (dinv[dst] factored out)
__device__ float g_dinv[MAXN];
__device__ int   g_deg[MAXN];
__device__ int   g_rowstart[MAXN];
__device__ int   g_bsum[256];
__device__ int   g_is64;

// ---------------------------------------------------------------------------
__device__ __forceinline__ uint32_t smem_u32(const void* p) {
    uint32_t a;
    asm("{ .reg .u64 t; cvta.to.shared.u64 t, %1; cvt.u32.u64 %0, t; }" : "=r"(a) : "l"(p));
    return a;
}
__device__ __forceinline__ void ldm_x4(uint32_t* r, uint32_t addr) {
    asm volatile("ldmatrix.sync.aligned.m8n8.x4.shared.b16 {%0,%1,%2,%3}, [%4];"
                 : "=r"(r[0]), "=r"(r[1]), "=r"(r[2]), "=r"(r[3]) : "r"(addr));
}
__device__ __forceinline__ void ldm_x4_t(uint32_t* r, uint32_t addr) {
    asm volatile("ldmatrix.sync.aligned.m8n8.x4.trans.shared.b16 {%0,%1,%2,%3}, [%4];"
                 : "=r"(r[0]), "=r"(r[1]), "=r"(r[2]), "=r"(r[3]) : "r"(addr));
}
__device__ __forceinline__ void mma_bf16(float* c, const uint32_t* a, const uint32_t* b) {
    asm volatile(
        "mma.sync.aligned.m16n8k16.row.col.f32.bf16.bf16.f32 "
        "{%0,%1,%2,%3}, {%4,%5,%6,%7}, {%8,%9}, {%0,%1,%2,%3};"
        : "+f"(c[0]), "+f"(c[1]), "+f"(c[2]), "+f"(c[3])
        : "r"(a[0]), "r"(a[1]), "r"(a[2]), "r"(a[3]), "r"(b[0]), "r"(b[1]));
}
__device__ __forceinline__ uint32_t bfbits(float v) {
    return (uint32_t)__bfloat16_as_ushort(__float2bfloat16(v));
}
__device__ __forceinline__ float bfval(uint32_t b) {
    return __bfloat162float(__ushort_as_bfloat16((unsigned short)b));
}

#define T_ELE (128 * LDT)
#define GEMM_SMEM (4 * T_ELE * 2)

// ---------------------------------------------------------------------------
// GEMM: g_y = x @ W via HMMA split precision (verified R4).
__global__ __launch_bounds__(256) void k_gemm_mma(const float* __restrict__ x,
                                                  const float* __restrict__ W, int n) {
    extern __shared__ __align__(16) char smem[];
    __nv_bfloat16* AH = (__nv_bfloat16*)smem;
    __nv_bfloat16* AL = AH + T_ELE;
    __nv_bfloat16* BH = AL + T_ELE;
    __nv_bfloat16* BL = BH + T_ELE;

    int tid = threadIdx.x;
    int wid = tid >> 5, lane = tid & 31;
    int row0 = blockIdx.x * 128;

#pragma unroll
    for (int i = 0; i < 16; i++) {
        int idx = tid + i * 256;
        int r = idx >> 5, f = idx & 31;
        int grow = row0 + r;
        float4 v = make_float4(0.f, 0.f, 0.f, 0.f);
        if (grow < n) v = *(const float4*)(x + (size_t)grow * DD + f * 4);
        uint32_t hx = bfbits(v.x), hy = bfbits(v.y), hz = bfbits(v.z), hw = bfbits(v.w);
        uint2 hh = make_uint2((hy << 16) | hx, (hw << 16) | hz);
        uint2 ll = make_uint2((bfbits(v.y - bfval(hy)) << 16) | bfbits(v.x - bfval(hx)),
                              (bfbits(v.w - bfval(hw)) << 16) | bfbits(v.z - bfval(hz)));
        *(uint2*)(AH + r * LDT + f * 4) = hh;
        *(uint2*)(AL + r * LDT + f * 4) = ll;
    }
#pragma unroll
    for (int i = 0; i < 16; i++) {
        int idx = tid + i * 256;
        int r = idx >> 5, f = idx & 31;
        float4 v = *(const float4*)(W + (size_t)r * DD + f * 4);
        uint32_t hx = bfbits(v.x), hy = bfbits(v.y), hz = bfbits(v.z), hw = bfbits(v.w);
        uint2 hh = make_uint2((hy << 16) | hx, (hw << 16) | hz);
        uint2 ll = make_uint2((bfbits(v.y - bfval(hy)) << 16) | bfbits(v.x - bfval(hx)),
                              (bfbits(v.w - bfval(hw)) << 16) | bfbits(v.z - bfval(hz)));
        *(uint2*)(BH + r * LDT + f * 4) = hh;
        *(uint2*)(BL + r * LDT + f * 4) = ll;
    }
    __syncthreads();

    int m0 = wid * 16;
    uint32_t a_off_h = smem_u32(AH + (m0 + (lane & 15)) * LDT + (lane >> 4) * 8);
    uint32_t a_off_l = a_off_h + (uint32_t)(T_ELE * 2);

    float acc[16][4];
#pragma unroll
    for (int j = 0; j < 16; j++)
#pragma unroll
        for (int q = 0; q < 4; q++) acc[j][q] = 0.0f;

#pragma unroll
    for (int k = 0; k < 8; k++) {
        uint32_t ah[4], al[4];
        ldm_x4(ah, a_off_h + k * 32);
        ldm_x4(al, a_off_l + k * 32);
        uint32_t b_base = smem_u32(BH + (k * 16 + (lane & 15)) * LDT + (lane >> 4) * 8);
#pragma unroll
        for (int j2 = 0; j2 < 8; j2++) {
            uint32_t bh[4], bl[4];
            ldm_x4_t(bh, b_base + j2 * 32);
            ldm_x4_t(bl, b_base + j2 * 32 + (uint32_t)(T_ELE * 2));
            mma_bf16(acc[2 * j2],     ah, bh);
            mma_bf16(acc[2 * j2],     ah, bl);
            mma_bf16(acc[2 * j2],     al, bh);
            mma_bf16(acc[2 * j2 + 1], ah, bh + 2);
            mma_bf16(acc[2 * j2 + 1], ah, bl + 2);
            mma_bf16(acc[2 * j2 + 1], al, bh + 2);
        }
    }

    int r_lo = row0 + m0 + (lane >> 2);
    int r_hi = r_lo + 8;
    int cbase = (lane & 3) * 2;
#pragma unroll
    for (int j = 0; j < 16; j++) {
        int col = j * 8 + cbase;
        if (r_lo < n) *(float2*)(g_y + (size_t)r_lo * DD + col) = make_float2(acc[j][0], acc[j][1]);
        if (r_hi < n) *(float2*)(g_y + (size_t)r_hi * DD + col) = make_float2(acc[j][2], acc[j][3]);
    }
}

// ---------------------------------------------------------------------------
// P1: zero deg + detect dtype.
__global__ void k_prep1(const unsigned int* __restrict__ raw, int n) {
    int i = blockIdx.x * blockDim.x + threadIdx.x;
    if (i < n) g_deg[i] = 0;
    if (i == 0) {
        int ok64 = (raw[1] == 0u) && (raw[3] == 0u) && (raw[5] == 0u) &&
                   (raw[7] == 0u) && (raw[9] == 0u) && (raw[11] == 0u);
        g_is64 = ok64 ? 1 : 0;
    }
}

// P2: convert edges + count degree; tail blocks copy x0 (independent work).
__global__ void k_prep2(const void* __restrict__ raw, int E, int nb_e,
                        const float* __restrict__ emb, float* __restrict__ x0, int n) {
    int b = blockIdx.x;
    if (b < nb_e) {
        int e = b * blockDim.x + threadIdx.x;
        if (e >= E) return;
        int s, d;
        if (g_is64) {
            const long long* p = (const long long*)raw;
            s = (int)p[e]; d = (int)p[e + E];
        } else {
            const int* p = (const int*)raw;
            s = p[e]; d = p[e + E];
        }
        g_src[e] = s; g_dst[e] = d;
        g_off[e] = atomicAdd(&g_deg[d], 1);
    } else {
        int i = (b - nb_e) * blockDim.x + threadIdx.x;
        if (i < n * (DD / 4)) ((float4*)x0)[i] = ((const float4*)emb)[i];
    }
}

// Scan pass 1 (per-block inclusive) + dinv.
__global__ void k_scan1(int n) {
    __shared__ int sh[SCAN_B];
    int i = blockIdx.x * SCAN_B + threadIdx.x;
    int v = (i < n) ? g_deg[i] : 0;
    if (i < n) g_dinv[i] = rsqrtf((float)(v + 1));
    sh[threadIdx.x] = v;
    __syncthreads();
#pragma unroll
    for (int off = 1; off < SCAN_B; off <<= 1) {
        int t = (threadIdx.x >= off) ? sh[threadIdx.x - off] : 0;
        __syncthreads();
        sh[threadIdx.x] += t;
        __syncthreads();
    }
    if (i < n) g_rowstart[i] = sh[threadIdx.x] - v;
    if (threadIdx.x == SCAN_B - 1) g_bsum[blockIdx.x] = sh[SCAN_B - 1];
}

// Scan pass 2: each block computes its own prefix of g_bsum (no serial kernel).
__global__ void k_scan3(int n) {
    __shared__ int s_off;
    int gb = blockIdx.x >> 1;   // scan1 block index (blockDim 256, SCAN_B 512)
    if (threadIdx.x < 32) {
        int acc = 0;
        for (int b = threadIdx.x; b < gb; b += 32) acc += g_bsum[b];
#pragma unroll
        for (int o = 16; o; o >>= 1) acc += __shfl_xor_sync(0xFFFFFFFFu, acc, o);
        if (threadIdx.x == 0) s_off = acc;
    }
    __syncthreads();
    int i = blockIdx.x * blockDim.x + threadIdx.x;
    if (i < n) g_rowstart[i] += s_off;
}

// Fill CSR: pos = rowstart[dst] + off[e]; weight = dinv[src] only.
__global__ void k_fill(int E) {
    int e = blockIdx.x * blockDim.x + threadIdx.x;
    if (e >= E) return;
    int s = g_src[e], d = g_dst[e];
    int pos = g_rowstart[d] + g_off[e];
    g_csrc[pos] = s;
    g_cw[pos]   = g_dinv[s];
}

// ---------------------------------------------------------------------------
// Aggregate: xout = bias + dinv^2*y[i] + dinv * sum_e dinv[s]*y[s].
// One warp per node.  Last layer also writes total = x0+x1+x2+xout.
__global__ __launch_bounds__(256) void k_aggregate(const float* __restrict__ bias,
                                                   float* __restrict__ xout,
                                                   float* __restrict__ total,
                                                   const float* __restrict__ xbase,
                                                   int n) {
    int t = blockIdx.x * blockDim.x + threadIdx.x;
    int node = t >> 5, lane = t & 31;
    if (node >= n) return;

    const float4* y4 = (const float4*)g_y;
    float ex = 0.f, ey = 0.f, ez = 0.f, ew = 0.f;

    int st  = g_rowstart[node];
    int cnt = g_deg[node];
    int k = 0;
    for (; k + 3 < cnt; k += 4) {
        int   s0 = g_csrc[st + k],     s1 = g_csrc[st + k + 1];
        int   s2 = g_csrc[st + k + 2], s3 = g_csrc[st + k + 3];
        float w0 = g_cw[st + k],       w1 = g_cw[st + k + 1];
        float w2 = g_cw[st + k + 2],   w3 = g_cw[st + k + 3];
        float4 v0 = __ldcg(y4 + (size_t)s0 * 32 + lane);
        float4 v1 = __ldcg(y4 + (size_t)s1 * 32 + lane);
        float4 v2 = __ldcg(y4 + (size_t)s2 * 32 + lane);
        float4 v3 = __ldcg(y4 + (size_t)s3 * 32 + lane);
        ex = fmaf(v0.x, w0, ex); ey = fmaf(v0.y, w0, ey);
        ez = fmaf(v0.z, w0, ez); ew = fmaf(v0.w, w0, ew);
        ex = fmaf(v1.x, w1, ex); ey = fmaf(v1.y, w1, ey);
        ez = fmaf(v1.z, w1, ez); ew = fmaf(v1.w, w1, ew);
        ex = fmaf(v2.x, w2, ex); ey = fmaf(v2.y, w2, ey);
        ez = fmaf(v2.z, w2, ez); ew = fmaf(v2.w, w2, ew);
        ex = fmaf(v3.x, w3, ex); ey = fmaf(v3.y, w3, ey);
        ez = fmaf(v3.z, w3, ez); ew = fmaf(v3.w, w3, ew);
    }
    for (; k < cnt; k++) {
        int   s0 = g_csrc[st + k];
        float w0 = g_cw[st + k];
        float4 v0 = __ldcg(y4 + (size_t)s0 * 32 + lane);
        ex = fmaf(v0.x, w0, ex); ey = fmaf(v0.y, w0, ey);
        ez = fmaf(v0.z, w0, ez); ew = fmaf(v0.w, w0, ew);
    }

    float s  = g_dinv[node];
    float s2 = s * s;
    float4 bb = ((const float4*)bias)[lane];
    float4 vs = y4[(size_t)node * 32 + lane];
    float ax = bb.x + fmaf(vs.x, s2, s * ex);
    float ay = bb.y + fmaf(vs.y, s2, s * ey);
    float az = bb.z + fmaf(vs.z, s2, s * ez);
    float aw = bb.w + fmaf(vs.w, s2, s * ew);

    size_t idx = (size_t)node * 32 + lane;
    ((float4*)xout)[idx] = make_float4(ax, ay, az, aw);

    if (total) {
        size_t nd4 = (size_t)n * 32;
        const float4* xb = (const float4*)xbase;
        float4 a = xb[idx], b2 = xb[nd4 + idx], c = xb[2 * nd4 + idx];
        ((float4*)total)[idx] = make_float4(a.x + b2.x + c.x + ax,
                                            a.y + b2.y + c.y + ay,
                                            a.z + b2.z + c.z + az,
                                            a.w + b2.w + c.w + aw);
    }
}

// ---------------------------------------------------------------------------
extern "C" void kernel_launch(void* const* d_in, const int* in_sizes, int n_in,
                              void* d_out, int out_size) {
    const float* item_emb = (const float*)d_in[0];
    const float* weights  = (const float*)d_in[1];
    const float* biases   = (const float*)d_in[2];
    const void*  edge_raw = d_in[3];

    int n = out_size / (5 * DD);
    int E = in_sizes[3] / 2;
    int emb_off = in_sizes[0] - n * DD;
    float* out = (float*)d_out;

    static bool attr_set = false;
    if (!attr_set) {
        cudaFuncSetAttribute(k_gemm_mma, cudaFuncAttributeMaxDynamicSharedMemorySize, GEMM_SMEM);
        attr_set = true;
    }

    const int TB = 256;
    int nb_n    = (n + TB - 1) / TB;
    int nb_e    = (E + TB - 1) / TB;
    int nb_nd4  = (n * 32 + TB - 1) / TB;
    int nb_scan = (n + SCAN_B - 1) / SCAN_B;
    int nb_gemm = (n + 127) / 128;
    long long agg_threads = (long long)n * 32;
    int nb_agg = (int)((agg_threads + TB - 1) / TB);

    const float* x0_src = item_emb + emb_off;
    float* x0_dst = out + (size_t)n * DD;

    // GEMM_0 reads item_emb directly (x0 == item_emb[-n:]) — launch first.
    k_gemm_mma<<<nb_gemm, 256, GEMM_SMEM>>>(x0_src, weights, n);

    // CSR build (+ x0 copy fused into prep2's tail blocks)
    k_prep1<<<nb_n, TB>>>((const unsigned int*)edge_raw, n);
    k_prep2<<<nb_e + nb_nd4, TB>>>(edge_raw, E, nb_e, x0_src, x0_dst, n);
    k_scan1<<<nb_scan, SCAN_B>>>(n);
    k_scan3<<<nb_n, TB>>>(n);
    k_fill<<<nb_e, TB>>>(E);

    // Layers; GEMM_0 already issued.
    for (int l = 0; l < 3; l++) {
        const float* xin = out + (size_t)(l + 1) * n * DD;
        float* xout      = out + (size_t)(l + 2) * n * DD;
        if (l > 0)
            k_gemm_mma<<<nb_gemm, 256, GEMM_SMEM>>>(xin, weights + (size_t)l * DD * DD, n);
        k_aggregate<<<nb_agg, TB>>>(biases + (size_t)l * DD, xout,
                                    (l == 2) ? out : nullptr,
                                    out + (size_t)n * DD, n);
    }
}